// round 2
// baseline (speedup 1.0000x reference)
#include <cuda_runtime.h>
#include <stdint.h>

// ---------------- problem constants ----------------
#define N_BINS    84
#define NBP       96        // bins padded to 16*6
#define FFTLEN    2048
#define FREQ_BINS 1025
#define HOP       512
#define T_SAMPLES 8388608
#define N_FRAMES  16381

// ---------------- fused kernel W storage ----------------
// Layout: Wg[n][bin][2] = {Wr, Wi},  n in [0,2048), bin in [0,96)
__device__ float Wg[FFTLEN * NBP * 2];

// ---------------- f32x2 helpers ----------------
__device__ __forceinline__ uint64_t dup2(float x) {
    uint64_t r; asm("mov.b64 %0, {%1, %1};" : "=l"(r) : "f"(x)); return r;
}
__device__ __forceinline__ uint64_t pack2(float lo, float hi) {
    uint64_t r; asm("mov.b64 %0, {%1, %2};" : "=l"(r) : "f"(lo), "f"(hi)); return r;
}
__device__ __forceinline__ void unpack2(uint64_t v, float& lo, float& hi) {
    asm("mov.b64 {%0, %1}, %2;" : "=f"(lo), "=f"(hi) : "l"(v));
}
__device__ __forceinline__ void ffma2(uint64_t& acc, uint64_t a, uint64_t b) {
    asm("fma.rn.f32x2 %0, %1, %2, %0;" : "+l"(acc) : "l"(a), "l"(b));
}

// =====================================================================
// Kernel 1: precompute fused kernels
//   Wr[b,n] = sum_k kr[b,k]*wcos[k,n] - ki[b,k]*wsin[k,n]
//   Wi[b,n] = sum_k kr[b,k]*wsin[k,n] + ki[b,k]*wcos[k,n]
// Grid: 128 CTAs, each handles 16 n-columns and all 96 (padded) bins.
// =====================================================================
__global__ void __launch_bounds__(256) prep_kernel(
    const float* __restrict__ kr, const float* __restrict__ ki,
    const float* __restrict__ wcos, const float* __restrict__ wsin)
{
    __shared__ float kct[32 * NBP * 2];   // [kl][bin][{kr,ki}]  24 KB
    __shared__ float wct[32 * 16 * 2];    // [kl][nt][{cos,sin}]  4 KB

    const int tid   = threadIdx.x;
    const int n_t   = tid & 15;
    const int bin_t = tid >> 4;           // 16 groups x 6 bins
    const int n0    = blockIdx.x * 16;

    uint64_t acc[6];
#pragma unroll
    for (int i = 0; i < 6; i++) acc[i] = 0ull;

    for (int kt = 0; kt < 33; kt++) {     // 33*32 = 1056 >= 1025
        const int k0 = kt * 32;
        __syncthreads();                  // protect prior-tile reads
        // fill kr/ki tile (coalesced along k)
        for (int i = tid; i < NBP * 32; i += 256) {
            int b = i >> 5, kl = i & 31, kg = k0 + kl;
            float vr = 0.f, vi = 0.f;
            if (b < N_BINS && kg < FREQ_BINS) {
                vr = kr[b * FREQ_BINS + kg];
                vi = ki[b * FREQ_BINS + kg];
            }
            kct[kl * (NBP * 2) + b * 2]     = vr;
            kct[kl * (NBP * 2) + b * 2 + 1] = vi;
        }
        // fill wcos/wsin tile
        for (int i = tid; i < 32 * 16; i += 256) {
            int kl = i >> 4, nn = i & 15, kg = k0 + kl;
            float c = 0.f, s = 0.f;
            if (kg < FREQ_BINS) {
                c = wcos[kg * FFTLEN + n0 + nn];
                s = wsin[kg * FFTLEN + n0 + nn];
            }
            wct[kl * 32 + nn * 2]     = c;
            wct[kl * 32 + nn * 2 + 1] = s;
        }
        __syncthreads();
#pragma unroll 4
        for (int kl = 0; kl < 32; kl++) {
            float c = wct[kl * 32 + n_t * 2];
            float s = wct[kl * 32 + n_t * 2 + 1];
            uint64_t cs  = pack2(c, s);     // multiplies kr -> (kr*c, kr*s)
            uint64_t mcs = pack2(-s, c);    // multiplies ki -> (-ki*s, ki*c)
            const float* kp = &kct[kl * (NBP * 2) + bin_t * 12];
#pragma unroll
            for (int i = 0; i < 6; i++) {
                float vkr = kp[i * 2], vki = kp[i * 2 + 1];
                ffma2(acc[i], dup2(vkr), cs);
                ffma2(acc[i], dup2(vki), mcs);
            }
        }
    }
    const int n = n0 + n_t;
#pragma unroll
    for (int i = 0; i < 6; i++) {
        int b = bin_t * 6 + i;
        float wr, wi; unpack2(acc[i], wr, wi);
        Wg[n * (NBP * 2) + b * 2]     = wr;   // b>=84 stays exactly 0
        Wg[n * (NBP * 2) + b * 2 + 1] = wi;
    }
}

// =====================================================================
// Kernel 2: main CQT
//   out[b,f] = sqrt(Re^2 + Im^2),  (Re,Im)[b,f] = sum_n x[f*512+n]*W[b,n]
// CTA tile: 32 frames x 96 bins. 256 threads = 16 frame_t x 16 bin_t.
// Thread computes 2 frames (frame_t, frame_t+16) x 6 bins, re+im as f32x2.
// x window loaded to smem once (hop structure: rows of 512, stride-513 pad),
// W streamed in 32-wide K tiles, double buffered.
// =====================================================================
#define FT       32
#define KT       32
#define XROWS    35            // FT + 3
#define XSTRIDE  513           // odd stride -> conflict-free strided reads
#define WS_OFF   17956         // XROWS*XSTRIDE=17955, +1 pad -> 16B aligned
#define WBUF     (KT * NBP * 2)  // 6144 floats per buffer

__global__ void __launch_bounds__(256) cqt_main(
    const float* __restrict__ x, float* __restrict__ out)
{
    extern __shared__ float sm[];
    float* xs = sm;             // [XROWS][XSTRIDE]
    float* ws = sm + WS_OFF;    // [2][KT][NBP][2]

    const int tid     = threadIdx.x;
    const int frame_t = tid & 15;
    const int bin_t   = tid >> 4;
    const int f0      = blockIdx.x * FT;
    const int base    = f0 * HOP;

    // ---- load x window: rows g = f0 .. f0+34, 512 floats each ----
    for (int i = tid; i < XROWS * 512; i += 256) {
        int row = i >> 9, m = i & 511;
        int g = base + row * 512 + m;
        xs[row * XSTRIDE + m] = (g < T_SAMPLES) ? x[g] : 0.f;
    }

    // ---- prefetch W tile 0 ----
    const float4* wgv = reinterpret_cast<const float4*>(Wg);
    float4 pf[6];
#pragma unroll
    for (int q = 0; q < 6; q++) pf[q] = wgv[tid + 256 * q];
    {
        float4* wsv = reinterpret_cast<float4*>(ws);
#pragma unroll
        for (int q = 0; q < 6; q++) wsv[tid + 256 * q] = pf[q];
    }
    __syncthreads();

    uint64_t acc[2][6];
#pragma unroll
    for (int r = 0; r < 2; r++)
#pragma unroll
        for (int i = 0; i < 6; i++) acc[r][i] = 0ull;

    for (int t = 0; t < FFTLEN / KT; t++) {   // 64 K-tiles
        const int cur = t & 1;
        // prefetch next tile into registers
        if (t < 63) {
            const float4* p = wgv + (t + 1) * (KT * 48);
#pragma unroll
            for (int q = 0; q < 6; q++) pf[q] = p[tid + 256 * q];
        }
        const int n0 = t * KT;
        const int j  = n0 >> 9;          // constant within tile (512 % KT == 0)
        const int m0 = n0 & 511;
        const float* xb0 = &xs[(frame_t + j) * XSTRIDE + m0];
        const float* xb1 = xb0 + 16 * XSTRIDE;
        const float* wb  = &ws[cur * WBUF + bin_t * 12];
#pragma unroll 8
        for (int kk = 0; kk < KT; kk++) {
            uint64_t x0 = dup2(xb0[kk]);
            uint64_t x1 = dup2(xb1[kk]);
            const ulonglong2* wp =
                reinterpret_cast<const ulonglong2*>(wb + kk * (NBP * 2));
            ulonglong2 w01 = wp[0];
            ulonglong2 w23 = wp[1];
            ulonglong2 w45 = wp[2];
            ffma2(acc[0][0], w01.x, x0); ffma2(acc[1][0], w01.x, x1);
            ffma2(acc[0][1], w01.y, x0); ffma2(acc[1][1], w01.y, x1);
            ffma2(acc[0][2], w23.x, x0); ffma2(acc[1][2], w23.x, x1);
            ffma2(acc[0][3], w23.y, x0); ffma2(acc[1][3], w23.y, x1);
            ffma2(acc[0][4], w45.x, x0); ffma2(acc[1][4], w45.x, x1);
            ffma2(acc[0][5], w45.y, x0); ffma2(acc[1][5], w45.y, x1);
        }
        // write prefetched tile to the other buffer
        if (t < 63) {
            float4* wsv = reinterpret_cast<float4*>(ws + (cur ^ 1) * WBUF);
#pragma unroll
            for (int q = 0; q < 6; q++) wsv[tid + 256 * q] = pf[q];
        }
        __syncthreads();
    }

    // ---- magnitude + store ----
#pragma unroll
    for (int r = 0; r < 2; r++) {
        int f = f0 + frame_t + 16 * r;
        if (f >= N_FRAMES) continue;
#pragma unroll
        for (int i = 0; i < 6; i++) {
            int b = bin_t * 6 + i;
            if (b < N_BINS) {
                float re, im; unpack2(acc[r][i], re, im);
                out[b * N_FRAMES + f] = sqrtf(re * re + im * im);
            }
        }
    }
}

// =====================================================================
extern "C" void kernel_launch(void* const* d_in, const int* in_sizes, int n_in,
                              void* d_out, int out_size)
{
    const float* x    = (const float*)d_in[0];
    const float* wcos = (const float*)d_in[1];
    const float* wsin = (const float*)d_in[2];
    const float* kr   = (const float*)d_in[3];
    const float* ki   = (const float*)d_in[4];
    float* out = (float*)d_out;

    prep_kernel<<<128, 256>>>(kr, ki, wcos, wsin);

    const size_t smem = (WS_OFF + 2 * WBUF) * sizeof(float);  // ~121 KB
    cudaFuncSetAttribute(cqt_main, cudaFuncAttributeMaxDynamicSharedMemorySize,
                         (int)smem);
    cqt_main<<<(16384 / FT), 256, smem>>>(x, out);
}